// round 9
// baseline (speedup 1.0000x reference)
#include <cuda_runtime.h>
#include <cuda_bf16.h>

// Problem constants (match reference)
#define B_  32
#define S_  128
#define I_  64
#define H_  1024
#define T_  4          // NUM_TIME_STEPS
#define DECAY      0.9f
#define THRESHOLD  1.0f
#define BETA       5.0f

// Chunked-scan parameters (contraction |f'| <= 0.9; 40 warm-up s-steps =
// 160 substeps -> state error ~5e-6, far below the 1e-3 bar).
#define NCHUNK    4
#define CHUNK_S   (S_ / NCHUNK)   // 32
#define WARMUP_S  40
#define GROUP_S   8               // consumer waits for drive in groups of 8 s

#define TPB        256
#define K1_BLOCKS  (B_ * S_)                     // 4096 producer blocks
#define K2_BLOCKS  (B_ * NCHUNK * (H_ / TPB))    // 512 consumer blocks

// Scratch (device globals: no allocation, graph-safe)
__device__ float g_drive[(size_t)B_ * S_ * H_];  // 16 MB, L2-resident
__device__ int   g_flag[B_ * S_];                // per-(s,b) "drive row ready"

// ---------------------------------------------------------------------------
// Flag reset — runs before the fused kernel on every launch/replay.
// ---------------------------------------------------------------------------
__global__ void reset_kernel()
{
    const int i = blockIdx.x * 256 + threadIdx.x;
    if (i < B_ * S_) g_flag[i] = 0;
}

// ---------------------------------------------------------------------------
// LIF substep: sigmoid(BETA*(v-1)) = 0.5*tanh(0.5*BETA*(v-1)) + 0.5
// -> single MUFU (tanh.approx) per substep.
// ---------------------------------------------------------------------------
__device__ __forceinline__ float tanh_approx(float z)
{
    float r;
    asm("tanh.approx.f32 %0, %1;" : "=f"(r) : "f"(z));
    return r;
}

__device__ __forceinline__ void lif_substep(float& v, float d, float& spike)
{
    v = fmaf(DECAY, v, d);
    const float z = fmaf(0.5f * BETA, v, -0.5f * BETA * THRESHOLD);
    spike = fmaf(0.5f, tanh_approx(z), 0.5f);
    v -= spike * THRESHOLD;
}

// ---------------------------------------------------------------------------
// Fused kernel.
//  Blocks [0, 4096): PRODUCERS — drive[b,s,:] = sum_i enc[i,:]*x[b,s,i,:]
//    s-major block order so early sequence positions complete first.
//    After storing, release the (s,b) flag (fence + barrier + flag store).
//  Blocks [4096, 4608): CONSUMERS — chunked LIF scan for one (b,chunk,h-tile).
//    Spin (nanosleep) on the flags for each 8-step group, then scan.
//    Consumers are DRAM-idle (issue/MUFU work) so they hide entirely inside
//    the producers' DRAM-bound phase; only chunk-3's last group trails.
// ---------------------------------------------------------------------------
__global__ __launch_bounds__(TPB)
void fused_kernel(const float* __restrict__ x,
                  const float* __restrict__ enc,
                  float* __restrict__ out)
{
    const int bid = blockIdx.x;

    if (bid < K1_BLOCKS) {
        // ---------------- producer: one (s, b) drive row ----------------
        const int s  = bid >> 5;        // s-major: s = bid / 32
        const int b  = bid & (B_ - 1);  // b = bid % 32
        const int bs = b * S_ + s;      // drive/x layout index
        const int h4 = threadIdx.x;     // float4 column 0..255

        const float4* xp = reinterpret_cast<const float4*>(x + (size_t)bs * I_ * H_) + h4;
        const float4* ep = reinterpret_cast<const float4*>(enc) + h4;

        float4 a0 = make_float4(0.f, 0.f, 0.f, 0.f);
        float4 a1 = make_float4(0.f, 0.f, 0.f, 0.f);

#pragma unroll
        for (int i = 0; i < I_; i += 2) {
            const float4 xv0 = __ldcs(&xp[(i + 0) * (H_ / 4)]);
            const float4 xv1 = __ldcs(&xp[(i + 1) * (H_ / 4)]);
            const float4 ev0 = __ldg (&ep[(i + 0) * (H_ / 4)]);
            const float4 ev1 = __ldg (&ep[(i + 1) * (H_ / 4)]);
            a0.x = fmaf(ev0.x, xv0.x, a0.x);
            a0.y = fmaf(ev0.y, xv0.y, a0.y);
            a0.z = fmaf(ev0.z, xv0.z, a0.z);
            a0.w = fmaf(ev0.w, xv0.w, a0.w);
            a1.x = fmaf(ev1.x, xv1.x, a1.x);
            a1.y = fmaf(ev1.y, xv1.y, a1.y);
            a1.z = fmaf(ev1.z, xv1.z, a1.z);
            a1.w = fmaf(ev1.w, xv1.w, a1.w);
        }

        float4 r;
        r.x = a0.x + a1.x;
        r.y = a0.y + a1.y;
        r.z = a0.z + a1.z;
        r.w = a0.w + a1.w;
        reinterpret_cast<float4*>(g_drive)[(size_t)bs * (H_ / 4) + h4] = r;

        // Release: all threads' stores visible at L2, then set the flag.
        __threadfence();
        __syncthreads();
        if (threadIdx.x == 0)
            atomicExch(&g_flag[s * B_ + b], 1);

    } else {
        // ---------------- consumer: one (b, chunk, 256-h tile) ----------------
        const int bid2  = bid - K1_BLOCKS;       // 0..511
        const int chunk = bid2 >> 7;             // /128 -> 0..3
        const int b     = (bid2 >> 2) & (B_ - 1);
        const int hq    = bid2 & 3;
        const int h     = hq * TPB + threadIdx.x;

        const int s_own = chunk * CHUNK_S;
        int s_start = s_own - WARMUP_S;
        if (s_start < 0) s_start = 0;            // clamped chunks are exact
        const int s_end = s_own + CHUNK_S;

        const float* dp = g_drive + (size_t)b * S_ * H_ + h;
        float*       ob = out     + (size_t)b * S_ * T_ * H_ + h;

        float v = 0.0f;
        float spike;

        for (int g0 = s_start; g0 < s_end; g0 += GROUP_S) {
            int g1 = g0 + GROUP_S;
            if (g1 > s_end) g1 = s_end;

            // Wait until this group's drive rows are published.
            if (threadIdx.x == 0) {
                for (int s = g0; s < g1; s++) {
                    while (*((volatile int*)&g_flag[s * B_ + b]) == 0)
                        __nanosleep(64);
                }
            }
            __syncthreads();   // flag observed -> safe to read drive (L2 via ldcg)

            for (int s = g0; s < g1; s++) {
                const float d = __ldcg(dp + (size_t)s * H_);
                if (s < s_own) {
                    // warm-up: discard spikes
#pragma unroll
                    for (int t = 0; t < T_; t++)
                        lif_substep(v, d, spike);
                } else {
                    float* os = ob + (size_t)s * T_ * H_;
#pragma unroll
                    for (int t = 0; t < T_; t++) {
                        lif_substep(v, d, spike);
                        __stcs(os + (size_t)t * H_, spike);
                    }
                }
            }
        }

        // Last chunk owns the final state.
        if (chunk == NCHUNK - 1)
            out[(size_t)B_ * S_ * T_ * H_ + (size_t)b * H_ + h] = v;
    }
}

// ---------------------------------------------------------------------------
extern "C" void kernel_launch(void* const* d_in, const int* in_sizes, int n_in,
                              void* d_out, int out_size)
{
    const float* x   = (const float*)d_in[0];   // [32,128,64,1024] f32
    const float* enc = (const float*)d_in[1];   // [64,1024] f32
    float* out = (float*)d_out;                 // [32*512*1024 + 32*1024] f32

    reset_kernel<<<(B_ * S_ + 255) / 256, 256>>>();
    fused_kernel<<<K1_BLOCKS + K2_BLOCKS, TPB>>>(x, enc, out);
}

// round 10
// speedup vs baseline: 1.1111x; 1.1111x over previous
#include <cuda_runtime.h>
#include <cuda_bf16.h>

// Problem constants (match reference)
#define B_  32
#define S_  128
#define I_  64
#define H_  1024
#define T_  4          // NUM_TIME_STEPS
#define DECAY      0.9f
#define THRESHOLD  1.0f
#define BETA       5.0f

// Balanced chunked-scan parameters.
// Every lane executes exactly 62 s-steps:
//   chunk 0: owns s [0,62),   warm-up 0  (EXACT: true v0=0)
//   chunk 1: owns s [62,84),  warm-up s [22,62)   (40 steps)
//   chunk 2: owns s [84,106), warm-up s [44,84)   (40 steps)
//   chunk 3: owns s [106,128),warm-up s [66,106)  (40 steps)
// Contraction: |d(v_next)/dv| <= 0.9 globally -> 40 s-steps = 160 substeps
// shrink the cold-start error to ~5e-6 absolute. Far below the 1e-3 bar.
#define NCHUNK    4
#define WARMUP_S  40

// 16 MB scratch for drive[b,s,h] (device global: no allocation, graph-safe)
__device__ float g_drive[(size_t)B_ * S_ * H_];

// ---------------------------------------------------------------------------
// Kernel 1: drive[b,s,h] = sum_i enc[i,h] * x[b,s,i,h]
// ~86% of HBM spec on 1.09 GB moved — at the achievable roofline. Unchanged.
// ---------------------------------------------------------------------------
#define K1_TPB 256

__global__ __launch_bounds__(K1_TPB)
void drive_kernel(const float* __restrict__ x,
                  const float* __restrict__ enc,
                  float* __restrict__ drive)
{
    const int idx = blockIdx.x * K1_TPB + threadIdx.x;  // 0 .. B*S*(H/4)-1
    const int h4  = idx & (H_ / 4 - 1);                 // float4 column
    const int bs  = idx >> 8;                           // fused (b*S + s)

    const float4* xp = reinterpret_cast<const float4*>(x + (size_t)bs * I_ * H_) + h4;
    const float4* ep = reinterpret_cast<const float4*>(enc) + h4;

    float4 a0 = make_float4(0.f, 0.f, 0.f, 0.f);
    float4 a1 = make_float4(0.f, 0.f, 0.f, 0.f);

#pragma unroll
    for (int i = 0; i < I_; i += 2) {
        const float4 xv0 = __ldcs(&xp[(i + 0) * (H_ / 4)]);
        const float4 xv1 = __ldcs(&xp[(i + 1) * (H_ / 4)]);
        const float4 ev0 = __ldg (&ep[(i + 0) * (H_ / 4)]);
        const float4 ev1 = __ldg (&ep[(i + 1) * (H_ / 4)]);
        a0.x = fmaf(ev0.x, xv0.x, a0.x);
        a0.y = fmaf(ev0.y, xv0.y, a0.y);
        a0.z = fmaf(ev0.z, xv0.z, a0.z);
        a0.w = fmaf(ev0.w, xv0.w, a0.w);
        a1.x = fmaf(ev1.x, xv1.x, a1.x);
        a1.y = fmaf(ev1.y, xv1.y, a1.y);
        a1.z = fmaf(ev1.z, xv1.z, a1.z);
        a1.w = fmaf(ev1.w, xv1.w, a1.w);
    }

    float4 r;
    r.x = a0.x + a1.x;
    r.y = a0.y + a1.y;
    r.z = a0.z + a1.z;
    r.w = a0.w + a1.w;
    reinterpret_cast<float4*>(drive)[idx] = r;   // L2-resident for kernel 2
}

// ---------------------------------------------------------------------------
// Kernel 2: balanced chunked LIF scan with 2-way ILP (h-pairs).
//  - one thread owns TWO adjacent h columns: float2 drive load, two
//    independent LIF chains (interleaved -> 2 substeps per chain latency),
//    float2 spike store (half the STG issues).
//  - sigmoid via tanh.approx: one MUFU per substep.
//  - balanced chunks: every lane runs exactly 62 s-steps, blocks uniform.
// ---------------------------------------------------------------------------
#define K2_TPB 256

__device__ __forceinline__ float tanh_approx(float z)
{
    float r;
    asm("tanh.approx.f32 %0, %1;" : "=f"(r) : "f"(z));
    return r;
}

__device__ __forceinline__ void lif_substep2(float& v0, float& v1, float d0, float d1,
                                             float& sp0, float& sp1)
{
    v0 = fmaf(DECAY, v0, d0);
    v1 = fmaf(DECAY, v1, d1);
    const float z0 = fmaf(0.5f * BETA, v0, -0.5f * BETA * THRESHOLD);
    const float z1 = fmaf(0.5f * BETA, v1, -0.5f * BETA * THRESHOLD);
    sp0 = fmaf(0.5f, tanh_approx(z0), 0.5f);
    sp1 = fmaf(0.5f, tanh_approx(z1), 0.5f);
    v0 -= sp0 * THRESHOLD;
    v1 -= sp1 * THRESHOLD;
}

__global__ __launch_bounds__(K2_TPB)
void lif_scan_kernel(const float* __restrict__ drive,
                     float* __restrict__ out)
{
    // 256 blocks: bid = chunk*(B_*2) + b*2 + half
    const int bid   = blockIdx.x;
    const int chunk = bid >> 6;                  // /(B_*2) -> 0..3
    const int rem   = bid & 63;
    const int b     = rem >> 1;
    const int half  = rem & 1;
    const int h2    = half * K2_TPB + threadIdx.x;   // float2 column 0..511

    // Balanced ownership: chunk0 owns 62 steps, chunks 1..3 own 22 each.
    const int s_own   = (chunk == 0) ? 0 : (62 + 22 * (chunk - 1));
    const int s_end   = (chunk == 0) ? 62 : (s_own + 22);
    const int s_start = (chunk == 0) ? 0 : (s_own - WARMUP_S);

    const float2* dp = reinterpret_cast<const float2*>(drive + (size_t)b * S_ * H_) + h2;
    float*        ob = out + (size_t)b * S_ * T_ * H_ + 2 * h2;

    float v0 = 0.0f, v1 = 0.0f;
    float sp0, sp1;

    // Warm-up: run both recurrences, discard spikes.
    for (int s = s_start; s < s_own; s++) {
        const float2 d = __ldg(dp + (size_t)s * (H_ / 2));
#pragma unroll
        for (int t = 0; t < T_; t++)
            lif_substep2(v0, v1, d.x, d.y, sp0, sp1);
    }

    // Owned range: store spikes (float2).
    for (int s = s_own; s < s_end; s++) {
        const float2 d = __ldg(dp + (size_t)s * (H_ / 2));
        float* os = ob + (size_t)s * T_ * H_;
#pragma unroll
        for (int t = 0; t < T_; t++) {
            lif_substep2(v0, v1, d.x, d.y, sp0, sp1);
            float2 sp = make_float2(sp0, sp1);
            __stcs(reinterpret_cast<float2*>(os + (size_t)t * H_), sp);
        }
    }

    // Last chunk owns the final state.
    if (chunk == NCHUNK - 1) {
        float* vf = out + (size_t)B_ * S_ * T_ * H_ + (size_t)b * H_ + 2 * h2;
        __stcs(reinterpret_cast<float2*>(vf), make_float2(v0, v1));
    }
}

// ---------------------------------------------------------------------------
extern "C" void kernel_launch(void* const* d_in, const int* in_sizes, int n_in,
                              void* d_out, int out_size)
{
    const float* x   = (const float*)d_in[0];   // [32,128,64,1024] f32
    const float* enc = (const float*)d_in[1];   // [64,1024] f32
    float* out = (float*)d_out;                 // [32*512*1024 + 32*1024] f32

    float* drive = nullptr;
    cudaGetSymbolAddress((void**)&drive, g_drive);   // host-side, graph-safe

    const int k1_blocks = (B_ * S_ * (H_ / 4)) / K1_TPB;   // 4096
    drive_kernel<<<k1_blocks, K1_TPB>>>(x, enc, drive);

    const int k2_blocks = NCHUNK * B_ * 2;                 // 256
    lif_scan_kernel<<<k2_blocks, K2_TPB>>>(drive, out);
}

// round 11
// speedup vs baseline: 1.1175x; 1.0058x over previous
#include <cuda_runtime.h>
#include <cuda_bf16.h>

// Problem constants (match reference)
#define B_  32
#define S_  128
#define I_  64
#define H_  1024
#define T_  4          // NUM_TIME_STEPS
#define DECAY      0.9f
#define THRESHOLD  1.0f
#define BETA       5.0f

// Balanced chunked-scan parameters.
// Every lane executes exactly 62 s-steps:
//   chunk 0: owns s [0,62),   warm-up 0  (EXACT: true v0=0)
//   chunk 1: owns s [62,84),  warm-up s [22,62)   (40 steps)
//   chunk 2: owns s [84,106), warm-up s [44,84)   (40 steps)
//   chunk 3: owns s [106,128),warm-up s [66,106)  (40 steps)
// Contraction: |d(v_next)/dv| <= 0.9 globally -> 160 warm substeps shrink the
// cold-start error to ~5e-6 absolute; far below the 1e-3 bar.
#define NCHUNK    4
#define WARMUP_S  40

// 16 MB scratch for drive[b,s,h] (device global: no allocation, graph-safe)
__device__ float g_drive[(size_t)B_ * S_ * H_];

// ---------------------------------------------------------------------------
// Kernel 1: drive[b,s,h] = sum_i enc[i,h] * x[b,s,i,h]
// ~86% of HBM spec on 1.09 GB moved — at the achievable roofline. Unchanged.
// ---------------------------------------------------------------------------
#define K1_TPB 256

__global__ __launch_bounds__(K1_TPB)
void drive_kernel(const float* __restrict__ x,
                  const float* __restrict__ enc,
                  float* __restrict__ drive)
{
    const int idx = blockIdx.x * K1_TPB + threadIdx.x;  // 0 .. B*S*(H/4)-1
    const int h4  = idx & (H_ / 4 - 1);                 // float4 column
    const int bs  = idx >> 8;                           // fused (b*S + s)

    const float4* xp = reinterpret_cast<const float4*>(x + (size_t)bs * I_ * H_) + h4;
    const float4* ep = reinterpret_cast<const float4*>(enc) + h4;

    float4 a0 = make_float4(0.f, 0.f, 0.f, 0.f);
    float4 a1 = make_float4(0.f, 0.f, 0.f, 0.f);

#pragma unroll
    for (int i = 0; i < I_; i += 2) {
        const float4 xv0 = __ldcs(&xp[(i + 0) * (H_ / 4)]);
        const float4 xv1 = __ldcs(&xp[(i + 1) * (H_ / 4)]);
        const float4 ev0 = __ldg (&ep[(i + 0) * (H_ / 4)]);
        const float4 ev1 = __ldg (&ep[(i + 1) * (H_ / 4)]);
        a0.x = fmaf(ev0.x, xv0.x, a0.x);
        a0.y = fmaf(ev0.y, xv0.y, a0.y);
        a0.z = fmaf(ev0.z, xv0.z, a0.z);
        a0.w = fmaf(ev0.w, xv0.w, a0.w);
        a1.x = fmaf(ev1.x, xv1.x, a1.x);
        a1.y = fmaf(ev1.y, xv1.y, a1.y);
        a1.z = fmaf(ev1.z, xv1.z, a1.z);
        a1.w = fmaf(ev1.w, xv1.w, a1.w);
    }

    float4 r;
    r.x = a0.x + a1.x;
    r.y = a0.y + a1.y;
    r.z = a0.z + a1.z;
    r.w = a0.w + a1.w;
    reinterpret_cast<float4*>(drive)[idx] = r;   // L2-resident for kernel 2
}

// ---------------------------------------------------------------------------
// Kernel 2: balanced chunked LIF scan, ILP-2 (h-pairs), 2-deep drive prefetch.
//  - drive loads for s+1 and s+2 are issued BEFORE the substep chain for s,
//    so the ~250-cycle L2 latency is covered by ~224 cycles of compute and
//    never sits on the serial dependency chain (R9's mistake).
//  - sigmoid via tanh.approx: one MUFU per h-substep.
//  - 512 blocks x 128 threads: even wave tiling over 148 SMs.
// ---------------------------------------------------------------------------
#define K2_TPB 128

__device__ __forceinline__ float tanh_approx(float z)
{
    float r;
    asm("tanh.approx.f32 %0, %1;" : "=f"(r) : "f"(z));
    return r;
}

__device__ __forceinline__ void lif_substep2(float& v0, float& v1, float d0, float d1,
                                             float& sp0, float& sp1)
{
    v0 = fmaf(DECAY, v0, d0);
    v1 = fmaf(DECAY, v1, d1);
    const float z0 = fmaf(0.5f * BETA, v0, -0.5f * BETA * THRESHOLD);
    const float z1 = fmaf(0.5f * BETA, v1, -0.5f * BETA * THRESHOLD);
    sp0 = fmaf(0.5f, tanh_approx(z0), 0.5f);
    sp1 = fmaf(0.5f, tanh_approx(z1), 0.5f);
    v0 -= sp0 * THRESHOLD;
    v1 -= sp1 * THRESHOLD;
}

__global__ __launch_bounds__(K2_TPB)
void lif_scan_kernel(const float* __restrict__ drive,
                     float* __restrict__ out)
{
    // 512 blocks: bid = chunk*(B_*4) + b*4 + quarter
    const int bid   = blockIdx.x;
    const int chunk = bid >> 7;                      // /(B_*4) -> 0..3
    const int rem   = bid & 127;
    const int b     = rem >> 2;
    const int quar  = rem & 3;
    const int h2    = quar * K2_TPB + threadIdx.x;   // float2 column 0..511

    // Balanced ownership: chunk0 owns 62 steps, chunks 1..3 own 22 each.
    const int s_own   = (chunk == 0) ? 0 : (62 + 22 * (chunk - 1));
    const int s_end   = (chunk == 0) ? 62 : (s_own + 22);
    const int s_start = (chunk == 0) ? 0 : (s_own - WARMUP_S);

    const float2* dp = reinterpret_cast<const float2*>(drive + (size_t)b * S_ * H_) + h2;
    float*        ob = out + (size_t)b * S_ * T_ * H_ + 2 * h2;

    float v0 = 0.0f, v1 = 0.0f;
    float sp0, sp1;

    // 2-deep prefetch pipeline for the drive values.
    float2 dc = __ldg(dp + (size_t)s_start * (H_ / 2));                       // s
    float2 dn = (s_start + 1 < s_end)
              ? __ldg(dp + (size_t)(s_start + 1) * (H_ / 2))
              : make_float2(0.f, 0.f);                                        // s+1

    for (int s = s_start; s < s_end; s++) {
        // Issue load for s+2 before consuming dc — off the serial chain.
        float2 d2 = (s + 2 < s_end)
                  ? __ldg(dp + (size_t)(s + 2) * (H_ / 2))
                  : make_float2(0.f, 0.f);

        if (s >= s_own) {
            float* os = ob + (size_t)s * T_ * H_;
#pragma unroll
            for (int t = 0; t < T_; t++) {
                lif_substep2(v0, v1, dc.x, dc.y, sp0, sp1);
                __stcs(reinterpret_cast<float2*>(os + (size_t)t * H_),
                       make_float2(sp0, sp1));
            }
        } else {
            // warm-up: discard spikes
#pragma unroll
            for (int t = 0; t < T_; t++)
                lif_substep2(v0, v1, dc.x, dc.y, sp0, sp1);
        }

        dc = dn;
        dn = d2;
    }

    // Last chunk owns the final state.
    if (chunk == NCHUNK - 1) {
        float* vf = out + (size_t)B_ * S_ * T_ * H_ + (size_t)b * H_ + 2 * h2;
        __stcs(reinterpret_cast<float2*>(vf), make_float2(v0, v1));
    }
}

// ---------------------------------------------------------------------------
extern "C" void kernel_launch(void* const* d_in, const int* in_sizes, int n_in,
                              void* d_out, int out_size)
{
    const float* x   = (const float*)d_in[0];   // [32,128,64,1024] f32
    const float* enc = (const float*)d_in[1];   // [64,1024] f32
    float* out = (float*)d_out;                 // [32*512*1024 + 32*1024] f32

    float* drive = nullptr;
    cudaGetSymbolAddress((void**)&drive, g_drive);   // host-side, graph-safe

    const int k1_blocks = (B_ * S_ * (H_ / 4)) / K1_TPB;   // 4096
    drive_kernel<<<k1_blocks, K1_TPB>>>(x, enc, drive);

    const int k2_blocks = NCHUNK * B_ * 4;                 // 512
    lif_scan_kernel<<<k2_blocks, K2_TPB>>>(drive, out);
}